// round 9
// baseline (speedup 1.0000x reference)
#include <cuda_runtime.h>
#include <cuda_bf16.h>

#define NQ      10
#define DIM     1024
#define LAYERS  8
#define THREADS 512

typedef unsigned long long u64;

__device__ __forceinline__ int sp10(int x) {
    // suffix parity: bit p = XOR of bits p..9  (CNOT-chain permutation)
    x ^= x >> 1; x ^= x >> 2; x ^= x >> 4; x ^= x >> 8;
    return x;
}
__device__ __forceinline__ int padi(int j) { return j + 2 * (j >> 5); }  // even-preserving pad

__device__ __forceinline__ u64 pfma(u64 a, u64 b, u64 c) {
    u64 d; asm("fma.rn.f32x2 %0, %1, %2, %3;" : "=l"(d) : "l"(a), "l"(b), "l"(c));
    return d;
}
__device__ __forceinline__ u64 pmul(u64 a, u64 b) {
    u64 d; asm("mul.rn.f32x2 %0, %1, %2;" : "=l"(d) : "l"(a), "l"(b));
    return d;
}
__device__ __forceinline__ u64 pack2(float lo, float hi) {
    u64 d; asm("mov.b64 %0, {%1, %2};" : "=l"(d) : "f"(lo), "f"(hi));
    return d;
}
__device__ __forceinline__ u64 dup2(float v) { return pack2(v, v); }
__device__ __forceinline__ float f_lo(u64 v) { return __int_as_float((int)(unsigned)v); }
__device__ __forceinline__ float f_hi(u64 v) { return __int_as_float((int)(v >> 32)); }

// One single-qubit gate on both packed amplitudes (SoA).
// Coefficient table g[7]: [m11x2][m12y2][-m12y2][m11y2][-m11y2][m12x2][-m12x2]
// hib = own value of the gate's j-bit. Uses m22=conj(m11), m21=-conj(m12):
//   nx = m11x*vx + (-t11y)*vy + t12x*ox + (-m12y)*oy
//   ny = m11x*vy + ( t11y)*vx + t12x*oy + ( m12y)*ox ,  t11y/t12x sign-flip when hib.
__device__ __forceinline__ void gate(u64& vx, u64& vy, int mask, const u64* g, int hib)
{
    u64 ox = __shfl_xor_sync(0xffffffffu, vx, mask);
    u64 oy = __shfl_xor_sync(0xffffffffu, vy, mask);
    u64 A  = g[0];
    u64 Dt = g[1];          // +m12y   (ny term)
    u64 Dh = g[2];          // -m12y   (nx term)
    u64 Bt = g[3 + hib];    // +t11y
    u64 Bh = g[4 - hib];    // -t11y
    u64 C  = g[5 + hib];    //  t12x
    u64 nx = pfma(A, vx, pfma(Bh, vy, pfma(C, ox, pmul(Dh, oy))));
    u64 ny = pfma(A, vy, pfma(Bt, vx, pfma(C, oy, pmul(Dt, ox))));
    vx = nx; vy = ny;
}

// outMode: 0 = real-part only (128,1024) f32; 1 = planar re-block then im-block
__global__ __launch_bounds__(THREADS)
void UnitaryR3Ansatz_kernel(const float* __restrict__ inp,
                            const float* __restrict__ params,
                            float* __restrict__ outF,
                            int outMode)
{
    const int b    = blockIdx.x;    // row 0..127
    const int copy = b >> 2;        // jnp.repeat(M, 4)
    const int t    = threadIdx.x;   // 0..511
    const int l    = t & 31;
    const int w    = t >> 5;        // 0..15

    __shared__ u64 cf[LAYERS][NQ][7];     // packed-dup gate coefficients
    __shared__ u64 s0buf[2 * 544];        // remap buffer A->B : X plane, Y plane
    __shared__ u64 s1buf[2 * 544];        // remap buffer B->A : X plane, Y plane
    float* X0 = (float*)s0buf;  float* Y0 = (float*)(s0buf + 544);
    float* X1 = (float*)s1buf;  float* Y1 = (float*)(s1buf + 544);

    // --- all 80 gate coefficient tables (reference _r3 + SU(2) reduction) ---
    if (t < LAYERS * NQ) {
        const int layer = t / NQ, q = t - layer * NQ;
        const float* a = params + ((size_t)(copy * LAYERS + layer) * NQ + q) * 3;
        const float omega = a[0], theta = a[1], phi = a[2];
        float s,  c;  sincosf(0.5f * theta,         &s,  &c);
        float sp, cp; sincosf(0.5f * (phi + omega), &sp, &cp);
        float sm, cm; sincosf(0.5f * (phi - omega), &sm, &cm);
        const float m11x =  cp * c, m11y = -sp * c;   // m11 = e^{-i(phi+omega)/2} c
        const float m12x = -cm * s, m12y = -sm * s;   // m12 = -e^{+i(phi-omega)/2} s
        u64* g = cf[layer][q];
        g[0] = dup2(m11x);
        g[1] = dup2(m12y);  g[2] = dup2(-m12y);
        g[3] = dup2(m11y);  g[4] = dup2(-m11y);
        g[5] = dup2(m12x);  g[6] = dup2(-m12x);
    }

    // --- layouts ---
    // A: j = [warp(4)=j9:6 | reg(1)=j5 | lane(5)=j4:0]   (gates: j-bits 0..4 = qubits 9..5)
    // B: j = [lane(5)=j9:5 | warp(4)=j4:1 | reg(1)=j0]   (gates: j-bits 5..9 = qubits 4..0)
    const int jA0  = (w << 6) | l;
    const int jA1  = jA0 | 32;
    const int stA0 = padi(jA0), stA1 = padi(jA1);
    const int ldB  = padi((l << 5) | (w << 1));     // even, pair-contiguous -> 64-bit slot
    const int ldE0 = padi(sp10(jA0));
    const int ldE1 = padi(sp10(jA1));

    // --- load input (real row -> packed complex state, layout A) ---
    u64 VX = pack2(inp[(size_t)b * DIM + jA0], inp[(size_t)b * DIM + jA1]);
    u64 VY = 0;   // (0.f, 0.f)

    __syncthreads();   // coefficients ready

    #pragma unroll
    for (int layer = 0; layer < LAYERS; ++layer) {
        // ===== A phase: qubits 9..5 on lane bits 0..4 =====
        #pragma unroll
        for (int k = 0; k < 5; ++k)
            gate(VX, VY, 1 << k, cf[layer][9 - k], (l >> k) & 1);

        // ===== remap A -> B (buffer s0) =====
        X0[stA0] = f_lo(VX);  X0[stA1] = f_hi(VX);
        Y0[stA0] = f_lo(VY);  Y0[stA1] = f_hi(VY);
        __syncthreads();
        VX = *(const u64*)(X0 + ldB);
        VY = *(const u64*)(Y0 + ldB);

        // ===== B phase: qubits 4..0 on lane bits 0..4 (j-bits 5..9) =====
        #pragma unroll
        for (int i = 0; i < 5; ++i)
            gate(VX, VY, 1 << i, cf[layer][4 - i], (l >> i) & 1);

        // ===== remap B -> A composed with entangler (buffer s1) =====
        *(u64*)(X1 + ldB) = VX;
        *(u64*)(Y1 + ldB) = VY;
        __syncthreads();
        VX = pack2(X1[ldE0], X1[ldE1]);
        VY = pack2(Y1[ldE0], Y1[ldE1]);
    }

    // --- output (layout A) ---
    const size_t base = (size_t)b * DIM;
    outF[base + jA0] = f_lo(VX);
    outF[base + jA1] = f_hi(VX);
    if (outMode != 0) {
        outF[(size_t)(128 * DIM) + base + jA0] = f_lo(VY);
        outF[(size_t)(128 * DIM) + base + jA1] = f_hi(VY);
    }
}

extern "C" void kernel_launch(void* const* d_in, const int* in_sizes, int n_in,
                              void* d_out, int out_size)
{
    const float* inp    = (const float*)d_in[0];
    const float* params = (const float*)d_in[1];
    if (n_in >= 2 && in_sizes[0] < in_sizes[1]) {
        inp    = (const float*)d_in[1];
        params = (const float*)d_in[0];
    }
    const int outMode = (out_size == 128 * DIM) ? 0 : 1;

    UnitaryR3Ansatz_kernel<<<128, THREADS>>>(inp, params, (float*)d_out, outMode);
}

// round 10
// speedup vs baseline: 1.4837x; 1.4837x over previous
#include <cuda_runtime.h>
#include <cuda_bf16.h>

#define NQ      10
#define DIM     1024
#define LAYERS  8
#define THREADS 256
#define PLANE   1088   // padi(1023)+1 rounded up

typedef unsigned long long u64;

__device__ __forceinline__ int sp10(int x) {
    // suffix parity: bit p = XOR of bits p..9  (CNOT-chain permutation)
    x ^= x >> 1; x ^= x >> 2; x ^= x >> 4; x ^= x >> 8;
    return x;
}
__device__ __forceinline__ int padi(int j) { return j + 2 * (j >> 5); }  // even-pair-preserving

__device__ __forceinline__ u64 pfma(u64 a, u64 b, u64 c) {
    u64 d; asm("fma.rn.f32x2 %0, %1, %2, %3;" : "=l"(d) : "l"(a), "l"(b), "l"(c));
    return d;
}
__device__ __forceinline__ u64 pmul(u64 a, u64 b) {
    u64 d; asm("mul.rn.f32x2 %0, %1, %2;" : "=l"(d) : "l"(a), "l"(b));
    return d;
}
__device__ __forceinline__ u64 pack2(float lo, float hi) {
    u64 d; asm("mov.b64 %0, {%1, %2};" : "=l"(d) : "f"(lo), "f"(hi));
    return d;
}
__device__ __forceinline__ void unpack2(u64 v, float& lo, float& hi) {
    asm("mov.b64 {%0, %1}, %2;" : "=f"(lo), "=f"(hi) : "l"(v));
}
__device__ __forceinline__ u64 swap64(u64 v) {
    u64 r;
    asm("{ .reg .b32 lo, hi; mov.b64 {lo, hi}, %1; mov.b64 %0, {hi, lo}; }"
        : "=l"(r) : "l"(v));
    return r;
}
__device__ __forceinline__ u64 dup2(float v) { return pack2(v, v); }

// coefficient table slots per gate (all u64):
// 0:A=dup(m11x) 1:B=dup(m11y) 2:NB=dup(-m11y) 3:C=dup(m12x) 4:NC=dup(-m12x)
// 5:D=dup(m12y) 6:ND=dup(-m12y) 7:Bmix=(m11y,-m11y) 8:NBmix=(-m11y,m11y)
// 9:Cmix=(m12x,-m12x)   [10,11 pad]
#define CFS 12

// Lane-shuffle gate: partner via shfl_xor(mask); per-thread sign mask S
// (0 or 0x80000000_80000000 per the gate's lane bit).
//   n.x = A vx + (NB^S) vy + (C^S) ox + ND oy
//   n.y = A vy + (B ^S) vx + (C^S) oy + D  ox
__device__ __forceinline__ void laneGate(u64& VX0, u64& VX1, u64& VY0, u64& VY1,
                                         int mask, const u64* g, u64 S)
{
    u64 ox0 = __shfl_xor_sync(0xffffffffu, VX0, mask);
    u64 oy0 = __shfl_xor_sync(0xffffffffu, VY0, mask);
    u64 ox1 = __shfl_xor_sync(0xffffffffu, VX1, mask);
    u64 oy1 = __shfl_xor_sync(0xffffffffu, VY1, mask);
    const u64 A = g[0], D = g[5], ND = g[6];
    const u64 Bs  = g[1] ^ S;
    const u64 NBs = g[2] ^ S;
    const u64 Cs  = g[3] ^ S;
    u64 nx0 = pfma(A, VX0, pfma(NBs, VY0, pfma(Cs, ox0, pmul(ND, oy0))));
    u64 ny0 = pfma(A, VY0, pfma(Bs,  VX0, pfma(Cs, oy0, pmul(D,  ox0))));
    u64 nx1 = pfma(A, VX1, pfma(NBs, VY1, pfma(Cs, ox1, pmul(ND, oy1))));
    u64 ny1 = pfma(A, VY1, pfma(Bs,  VX1, pfma(Cs, oy1, pmul(D,  ox1))));
    VX0 = nx0; VY0 = ny0; VX1 = nx1; VY1 = ny1;
}

// Across-pack gate: pack0 has gate-bit 0, pack1 has 1 (compile-time signs).
//   n0 = m11*a0 + m12*a1 ;  n1 = -conj(m12)*a0 + conj(m11)*a1
__device__ __forceinline__ void acrossGate(u64& VX0, u64& VX1, u64& VY0, u64& VY1,
                                           const u64* g)
{
    const u64 A = g[0], B = g[1], NB = g[2], C = g[3], NC = g[4], D = g[5], ND = g[6];
    u64 nx0 = pfma(A,  VX0, pfma(NB, VY0, pfma(C, VX1, pmul(ND, VY1))));
    u64 ny0 = pfma(A,  VY0, pfma(B,  VX0, pfma(C, VY1, pmul(D,  VX1))));
    u64 nx1 = pfma(NC, VX0, pfma(ND, VY0, pfma(A, VX1, pmul(B,  VY1))));
    u64 ny1 = pfma(NC, VY0, pfma(D,  VX0, pfma(A, VY1, pmul(NB, VX1))));
    VX0 = nx0; VY0 = ny0; VX1 = nx1; VY1 = ny1;
}

// Within-pack gate: halves of each u64 are the pair (lo: bit=0, hi: bit=1).
// Partner = half-swap; per-half signs baked into the *mix coefficient packs.
__device__ __forceinline__ void withinGate(u64& VX0, u64& VX1, u64& VY0, u64& VY1,
                                           const u64* g)
{
    const u64 A = g[0], D = g[5], ND = g[6];
    const u64 Bm = g[7], NBm = g[8], Cm = g[9];
    u64 ox0 = swap64(VX0), oy0 = swap64(VY0);
    u64 ox1 = swap64(VX1), oy1 = swap64(VY1);
    u64 nx0 = pfma(A, VX0, pfma(NBm, VY0, pfma(Cm, ox0, pmul(ND, oy0))));
    u64 ny0 = pfma(A, VY0, pfma(Bm,  VX0, pfma(Cm, oy0, pmul(D,  ox0))));
    u64 nx1 = pfma(A, VX1, pfma(NBm, VY1, pfma(Cm, ox1, pmul(ND, oy1))));
    u64 ny1 = pfma(A, VY1, pfma(Bm,  VX1, pfma(Cm, oy1, pmul(D,  ox1))));
    VX0 = nx0; VY0 = ny0; VX1 = nx1; VY1 = ny1;
}

// outMode: 0 = real-part only (128,1024) f32; 1 = planar re-block then im-block
__global__ __launch_bounds__(THREADS)
void UnitaryR3Ansatz_kernel(const float* __restrict__ inp,
                            const float* __restrict__ params,
                            float* __restrict__ outF,
                            int outMode)
{
    const int b    = blockIdx.x;    // row 0..127
    const int copy = b >> 2;        // jnp.repeat(M, 4)
    const int t    = threadIdx.x;   // 0..255
    const int l    = t & 31;
    const int w    = t >> 5;        // 0..7

    __shared__ __align__(16) u64 cf[LAYERS][NQ][CFS];
    __shared__ float X0[PLANE], Y0[PLANE];   // A->B buffer
    __shared__ float X1[PLANE], Y1[PLANE];   // B->A buffer

    // --- build coefficient tables (reference _r3 verbatim + SU(2) reduction) ---
    if (t < LAYERS * NQ) {
        const int layer = t / NQ, q = t - layer * NQ;
        const float* a = params + ((size_t)(copy * LAYERS + layer) * NQ + q) * 3;
        const float omega = a[0], theta = a[1], phi = a[2];
        float s,  c;  sincosf(0.5f * theta,         &s,  &c);
        float sp, cp; sincosf(0.5f * (phi + omega), &sp, &cp);
        float sm, cm; sincosf(0.5f * (phi - omega), &sm, &cm);
        const float m11x =  cp * c, m11y = -sp * c;   // m11 = e^{-i(phi+omega)/2} c
        const float m12x = -cm * s, m12y = -sm * s;   // m12 = -e^{+i(phi-omega)/2} s
        u64* g = cf[layer][q];
        g[0] = dup2(m11x);
        g[1] = dup2(m11y);   g[2] = dup2(-m11y);
        g[3] = dup2(m12x);   g[4] = dup2(-m12x);
        g[5] = dup2(m12y);   g[6] = dup2(-m12y);
        g[7] = pack2(m11y, -m11y);
        g[8] = pack2(-m11y, m11y);
        g[9] = pack2(m12x, -m12x);
    }

    // --- per-thread constants ---
    // layout A: j = [warp(3)=j9:7 | lane(5)=j6:2 | reg(2)=j1:0],  jA = 4t + r
    // layout B: j = [reg(2)=j9:8 | lane(5)=j7:3 | warp(3)=j2:0],  jB = (r<<8)|(l<<3)|w
    u64 S[5];
    #pragma unroll
    for (int k = 0; k < 5; ++k)
        S[k] = ((l >> k) & 1) ? 0x8000000080000000ull : 0ull;

    const int stA0 = padi(4 * t);          // A-side u64 write (pair r0,r1)
    const int stA1 = padi(4 * t + 2);      // (pair r2,r3)
    int iB[4], iE[4];
    #pragma unroll
    for (int r = 0; r < 4; ++r) {
        iB[r] = padi((r << 8) | (l << 3) | w);
        iE[r] = padi(sp10(4 * t + r));
    }

    // --- load input (layout A, coalesced float4) ---
    const float4 in4 = *(const float4*)(inp + (size_t)b * DIM + 4 * t);
    u64 VX0 = pack2(in4.x, in4.y);
    u64 VX1 = pack2(in4.z, in4.w);
    u64 VY0 = 0, VY1 = 0;

    __syncthreads();   // coefficient tables ready

    #pragma unroll 1
    for (int layer = 0; layer < LAYERS; ++layer) {
        const u64 (*G)[CFS] = cf[layer];

        // ===== layout A =====
        withinGate(VX0, VX1, VY0, VY1, G[9]);                // qubit 9 (j-bit 0)
        acrossGate(VX0, VX1, VY0, VY1, G[8]);                // qubit 8 (j-bit 1)
        #pragma unroll
        for (int k = 0; k < 5; ++k)                          // qubits 7..3 (lane bits 0..4)
            laneGate(VX0, VX1, VY0, VY1, 1 << k, G[7 - k], S[k]);

        // ===== remap A -> B =====
        *(u64*)(X0 + stA0) = VX0;  *(u64*)(X0 + stA1) = VX1;
        *(u64*)(Y0 + stA0) = VY0;  *(u64*)(Y0 + stA1) = VY1;
        __syncthreads();
        VX0 = pack2(X0[iB[0]], X0[iB[1]]);  VX1 = pack2(X0[iB[2]], X0[iB[3]]);
        VY0 = pack2(Y0[iB[0]], Y0[iB[1]]);  VY1 = pack2(Y0[iB[2]], Y0[iB[3]]);

        // ===== layout B =====
        withinGate(VX0, VX1, VY0, VY1, G[1]);                // qubit 1 (j-bit 8)
        acrossGate(VX0, VX1, VY0, VY1, G[0]);                // qubit 0 (j-bit 9)
        laneGate(VX0, VX1, VY0, VY1, 16, G[2], S[4]);        // qubit 2 (j-bit 7 = lane bit 4)

        // ===== remap B -> A composed with entangler =====
        {
            float f0, f1, f2, f3;
            unpack2(VX0, f0, f1); unpack2(VX1, f2, f3);
            X1[iB[0]] = f0; X1[iB[1]] = f1; X1[iB[2]] = f2; X1[iB[3]] = f3;
            unpack2(VY0, f0, f1); unpack2(VY1, f2, f3);
            Y1[iB[0]] = f0; Y1[iB[1]] = f1; Y1[iB[2]] = f2; Y1[iB[3]] = f3;
        }
        __syncthreads();
        VX0 = pack2(X1[iE[0]], X1[iE[1]]);  VX1 = pack2(X1[iE[2]], X1[iE[3]]);
        VY0 = pack2(Y1[iE[0]], Y1[iE[1]]);  VY1 = pack2(Y1[iE[2]], Y1[iE[3]]);
    }

    // --- output (layout A, coalesced float4) ---
    float x0, x1, x2, x3;
    unpack2(VX0, x0, x1); unpack2(VX1, x2, x3);
    *(float4*)(outF + (size_t)b * DIM + 4 * t) = make_float4(x0, x1, x2, x3);
    if (outMode != 0) {
        float y0, y1, y2, y3;
        unpack2(VY0, y0, y1); unpack2(VY1, y2, y3);
        *(float4*)(outF + (size_t)(128 * DIM) + (size_t)b * DIM + 4 * t) =
            make_float4(y0, y1, y2, y3);
    }
}

extern "C" void kernel_launch(void* const* d_in, const int* in_sizes, int n_in,
                              void* d_out, int out_size)
{
    const float* inp    = (const float*)d_in[0];
    const float* params = (const float*)d_in[1];
    if (n_in >= 2 && in_sizes[0] < in_sizes[1]) {
        inp    = (const float*)d_in[1];
        params = (const float*)d_in[0];
    }
    const int outMode = (out_size == 128 * DIM) ? 0 : 1;

    UnitaryR3Ansatz_kernel<<<128, THREADS>>>(inp, params, (float*)d_out, outMode);
}